// round 13
// baseline (speedup 1.0000x reference)
#include <cuda_runtime.h>
#include <cuda_fp16.h>
#include <cstdint>
#include <cstddef>

// ---------------- problem constants ----------------
#define N_Uc   8192
#define N_Ic   8192
#define D_INc  2048
#define D_Hc   2048
#define N_TOTc (N_Uc + N_Ic)

// ---------------- fp16 scratch (device globals; no allocs allowed) ----------------
__device__ __half g_inputH[(size_t)N_TOTc * D_INc];   // rn(input)  [16384][2048]
__device__ __half g_WH[(size_t)D_Hc * D_INc];         // rn(W)      [2048][2048]
__device__ __half g_adjH[(size_t)N_Uc * N_Ic];        // rn(adj)    [8192][8192]
__device__ __half g_supH[(size_t)N_TOTc * D_Hc];      // rn(support)[16384][2048]

// ---------------- PTX helpers ----------------
__device__ __forceinline__ uint32_t smem_u32(const void* p) {
    uint32_t a;
    asm("{ .reg .u64 t; cvta.to.shared.u64 t, %1; cvt.u32.u64 %0, t; }" : "=r"(a) : "l"(p));
    return a;
}
__device__ __forceinline__ void cp_async16(uint32_t s, const void* g) {
    asm volatile("cp.async.cg.shared.global [%0], [%1], 16;" :: "r"(s), "l"(g));
}
__device__ __forceinline__ void cp_commit() {
    asm volatile("cp.async.commit_group;" ::: "memory");
}
template<int N>
__device__ __forceinline__ void cp_wait() {
    asm volatile("cp.async.wait_group %0;" :: "n"(N) : "memory");
}
__device__ __forceinline__ void ldsm_x4(uint32_t& r0, uint32_t& r1, uint32_t& r2,
                                        uint32_t& r3, uint32_t addr) {
    asm volatile("ldmatrix.sync.aligned.m8n8.x4.shared.b16 {%0,%1,%2,%3}, [%4];"
                 : "=r"(r0), "=r"(r1), "=r"(r2), "=r"(r3) : "r"(addr));
}
__device__ __forceinline__ void ldsm_x4_t(uint32_t& r0, uint32_t& r1, uint32_t& r2,
                                          uint32_t& r3, uint32_t addr) {
    asm volatile("ldmatrix.sync.aligned.m8n8.x4.trans.shared.b16 {%0,%1,%2,%3}, [%4];"
                 : "=r"(r0), "=r"(r1), "=r"(r2), "=r"(r3) : "r"(addr));
}
__device__ __forceinline__ void mma_f16(float d[4], const uint32_t a[4],
                                        const uint32_t b[2], const float c[4]) {
    asm volatile(
        "mma.sync.aligned.m16n8k16.row.col.f32.f16.f16.f32 "
        "{%0,%1,%2,%3}, {%4,%5,%6,%7}, {%8,%9}, {%10,%11,%12,%13};"
        : "=f"(d[0]), "=f"(d[1]), "=f"(d[2]), "=f"(d[3])
        : "r"(a[0]), "r"(a[1]), "r"(a[2]), "r"(a[3]),
          "r"(b[0]), "r"(b[1]),
          "f"(c[0]), "f"(c[1]), "f"(c[2]), "f"(c[3]));
}

__device__ __forceinline__ void cvt8(const float* __restrict__ src,
                                     __half* __restrict__ dst) {
    float4 v0 = *reinterpret_cast<const float4*>(src);
    float4 v1 = *reinterpret_cast<const float4*>(src + 4);
    __half2 h0 = __floats2half2_rn(v0.x, v0.y);
    __half2 h1 = __floats2half2_rn(v0.z, v0.w);
    __half2 h2 = __floats2half2_rn(v1.x, v1.y);
    __half2 h3 = __floats2half2_rn(v1.z, v1.w);
    uint4 u;
    u.x = *reinterpret_cast<uint32_t*>(&h0);
    u.y = *reinterpret_cast<uint32_t*>(&h1);
    u.z = *reinterpret_cast<uint32_t*>(&h2);
    u.w = *reinterpret_cast<uint32_t*>(&h3);
    *reinterpret_cast<uint4*>(dst) = u;
}

// ============================================================================
// Kernel A (GEMM1): CTA 128x128x64, 4 warps (2x2), warp 64x64, 3-stage,
// single __syncthreads per iteration, 2 CTAs/SM. A K-contig, B [n][k] K-contig.
// (Round-10 form, measured 362us / tensor 62%.)
// ============================================================================
#define BMa 128
#define BNa 128
#define BKa 64
#define NSTGa 3
#define SKCa 144    // 64 halves = 128B -> 144
#define ASZa (BMa * SKCa)
#define BSZa (BNa * SKCa)
#define STGa (ASZa + BSZa)
#define SMEM_A_TOTAL (NSTGa * STGa)   // 110592

__launch_bounds__(128, 2)
__global__ void hgemmA(const __half* __restrict__ A, const __half* __restrict__ B,
                       const float* __restrict__ E, __half* __restrict__ C,
                       int K, int lda, int ldb, int ldc)
{
    extern __shared__ __align__(16) char smem[];
    const uint32_t sb = smem_u32(smem);

    const int tid  = threadIdx.x;
    const int lane = tid & 31;
    const int warp = tid >> 5;
    const int wm   = warp >> 1;
    const int wn   = warp & 1;
    const int q    = lane >> 3;
    const int r    = lane & 7;
    const int g    = lane >> 2;
    const int t    = lane & 3;

    const int m0 = blockIdx.y * BMa;
    const int n0 = blockIdx.x * BNa;

    float acc[4][8][4];
#pragma unroll
    for (int i = 0; i < 4; i++)
#pragma unroll
        for (int j = 0; j < 8; j++)
#pragma unroll
            for (int k = 0; k < 4; k++) acc[i][j][k] = 0.f;

    const uint32_t a_base = (uint32_t)((wm * 64 + r + (q & 1) * 8) * SKCa + (q >> 1) * 16);
    const uint32_t b_base = (uint32_t)((wn * 64 + r + (q >> 1) * 8) * SKCa + (q & 1) * 16);

    auto fill = [&](int s, int kt) {
        const uint32_t ab = sb + (uint32_t)s * STGa;
        const uint32_t bb = ab + ASZa;
        const int k0 = kt * BKa;
#pragma unroll
        for (int i = 0; i < 8; i++) {
            int ci = tid + i * 128, row = ci >> 3, c = ci & 7;
            cp_async16(ab + row * SKCa + c * 16,
                       A + (size_t)(m0 + row) * lda + k0 + c * 8);
        }
#pragma unroll
        for (int i = 0; i < 8; i++) {
            int ci = tid + i * 128, row = ci >> 3, c = ci & 7;
            cp_async16(bb + row * SKCa + c * 16,
                       B + (size_t)(n0 + row) * ldb + k0 + c * 8);
        }
        cp_commit();
    };

    const int T = K / BKa;
    fill(0, 0);
    fill(1, 1);

    int s = 0;
    for (int kt = 0; kt < T; kt++) {
        cp_wait<1>();
        __syncthreads();
        if (kt + 2 < T) {
            int ns = s + 2; if (ns >= NSTGa) ns -= NSTGa;
            fill(ns, kt + 2);
        } else {
            cp_commit();
        }

        const uint32_t aa = sb + (uint32_t)s * STGa + a_base;
        const uint32_t ba = sb + (uint32_t)s * STGa + ASZa + b_base;
#pragma unroll
        for (int ks = 0; ks < 4; ks++) {
            const uint32_t ak = aa + ks * 32;
            const uint32_t bk = ba + ks * 32;
            uint32_t af[4][4];
#pragma unroll
            for (int mt = 0; mt < 4; mt++)
                ldsm_x4(af[mt][0], af[mt][1], af[mt][2], af[mt][3], ak + mt * 16 * SKCa);
            uint32_t bf[8][2];
#pragma unroll
            for (int h = 0; h < 4; h++)
                ldsm_x4(bf[2*h][0], bf[2*h][1], bf[2*h+1][0], bf[2*h+1][1], bk + h * 16 * SKCa);
#pragma unroll
            for (int mt = 0; mt < 4; mt++)
#pragma unroll
                for (int nt = 0; nt < 8; nt++)
                    mma_f16(acc[mt][nt], af[mt], bf[nt], acc[mt][nt]);
        }
        if (++s == NSTGa) s = 0;
    }

#pragma unroll
    for (int mt = 0; mt < 4; mt++) {
        const int mr0 = m0 + wm * 64 + mt * 16 + g;
        const int mr1 = mr0 + 8;
#pragma unroll
        for (int nt = 0; nt < 8; nt++) {
            const int nc = n0 + wn * 64 + nt * 8 + 2 * t;
            const float bx = E[nc], by = E[nc + 1];
            *reinterpret_cast<__half2*>(&C[(size_t)mr0 * ldc + nc]) =
                __floats2half2_rn(acc[mt][nt][0] + bx, acc[mt][nt][1] + by);
            *reinterpret_cast<__half2*>(&C[(size_t)mr1 * ldc + nc]) =
                __floats2half2_rn(acc[mt][nt][2] + bx, acc[mt][nt][3] + by);
        }
    }
}

// ============================================================================
// Kernel B (GEMM2+GEMM3 merged): CTA 128x128x64, 8 warps (2x4), warp 64x32,
// 3-stage, single __syncthreads/iter, 2 CTAs/SM, hoisted/pipelined ldmatrix.
// (Round-11 form, tensor 64%.)
// ============================================================================
#define BMb 128
#define BNb 128
#define BKb 64
#define NSTGb 3
#define SKCb 144
#define SMCb 272
#define ASZb 18432  // max(128*144, 64*272)
#define BSZb (BKb * SMCb)              // 17408
#define STGb (ASZb + BSZb)             // 35840
#define SMEM_B_TOTAL (NSTGb * STGb)    // 107520

template<bool A_K_CONTIG>
__device__ __forceinline__ void gemmB_body(
    const __half* __restrict__ A, const __half* __restrict__ B,
    const float* __restrict__ E, float* __restrict__ C,
    int m0, int n0, uint32_t sb)
{
    const int K   = 8192;
    const int lda = N_Ic;
    const int ldb = D_Hc;
    const int ldc = D_Hc;

    const int tid  = threadIdx.x;
    const int lane = tid & 31;
    const int warp = tid >> 5;
    const int wm   = warp >> 2;
    const int wn   = warp & 3;
    const int q    = lane >> 3;
    const int r    = lane & 7;
    const int g    = lane >> 2;
    const int t    = lane & 3;

    float acc[4][4][4];
#pragma unroll
    for (int i = 0; i < 4; i++)
#pragma unroll
        for (int j = 0; j < 4; j++)
#pragma unroll
            for (int k = 0; k < 4; k++) acc[i][j][k] = 0.f;

    uint32_t a_base;
    if (A_K_CONTIG)
        a_base = (uint32_t)((wm * 64 + r + (q & 1) * 8) * SKCb + (q >> 1) * 16);
    else
        a_base = (uint32_t)((r + (q >> 1) * 8) * SMCb + (wm * 64 + (q & 1) * 8) * 2);
    const uint32_t b_base =
        (uint32_t)((r + (q & 1) * 8) * SMCb + (wn * 32 + (q >> 1) * 8) * 2);

    auto fill = [&](int s, int kt) {
        const uint32_t ab = sb + (uint32_t)s * STGb;
        const uint32_t bb = ab + ASZb;
        const int k0 = kt * BKb;
        if (A_K_CONTIG) {
#pragma unroll
            for (int i = 0; i < 4; i++) {
                int ci = tid + i * 256, row = ci >> 3, c = ci & 7;
                cp_async16(ab + row * SKCb + c * 16,
                           A + (size_t)(m0 + row) * lda + k0 + c * 8);
            }
        } else {
#pragma unroll
            for (int i = 0; i < 4; i++) {
                int ci = tid + i * 256, row = ci >> 4, c = ci & 15;
                cp_async16(ab + row * SMCb + c * 16,
                           A + (size_t)(k0 + row) * lda + m0 + c * 8);
            }
        }
#pragma unroll
        for (int i = 0; i < 4; i++) {
            int ci = tid + i * 256, row = ci >> 4, c = ci & 15;
            cp_async16(bb + row * SMCb + c * 16,
                       B + (size_t)(k0 + row) * ldb + n0 + c * 8);
        }
        cp_commit();
    };

    auto load_a = [&](uint32_t aa, int ks, uint32_t af[4][4]) {
        const uint32_t ak = A_K_CONTIG ? (aa + ks * 32) : (aa + ks * 16 * SMCb);
#pragma unroll
        for (int mt = 0; mt < 4; mt++) {
            const uint32_t addr = A_K_CONTIG ? (ak + mt * 16 * SKCb) : (ak + mt * 32);
            if (A_K_CONTIG) ldsm_x4  (af[mt][0], af[mt][1], af[mt][2], af[mt][3], addr);
            else            ldsm_x4_t(af[mt][0], af[mt][1], af[mt][2], af[mt][3], addr);
        }
    };
    auto load_b = [&](uint32_t ba, int ks, uint32_t bf[4][2]) {
        const uint32_t bk = ba + ks * 16 * SMCb;
#pragma unroll
        for (int h = 0; h < 2; h++)
            ldsm_x4_t(bf[2*h][0], bf[2*h][1], bf[2*h+1][0], bf[2*h+1][1], bk + h * 32);
    };

    const int T = K / BKb;
    fill(0, 0);
    fill(1, 1);

    int s = 0;
    for (int kt = 0; kt < T; kt++) {
        cp_wait<1>();
        __syncthreads();

        const uint32_t aa = sb + (uint32_t)s * STGb + a_base;
        const uint32_t ba = sb + (uint32_t)s * STGb + ASZb + b_base;

        uint32_t af[4][4], bf[4][2];
        load_a(aa, 0, af);
        load_b(ba, 0, bf);

        if (kt + 2 < T) {
            int ns = s + 2; if (ns >= NSTGb) ns -= NSTGb;
            fill(ns, kt + 2);
        } else {
            cp_commit();
        }

#pragma unroll
        for (int ks = 0; ks < 4; ks++) {
#pragma unroll
            for (int mt = 0; mt < 4; mt++)
#pragma unroll
                for (int nt = 0; nt < 4; nt++)
                    mma_f16(acc[mt][nt], af[mt], bf[nt], acc[mt][nt]);
            if (ks < 3) {
                load_a(aa, ks + 1, af);
                load_b(ba, ks + 1, bf);
            }
        }
        if (++s == NSTGb) s = 0;
    }

#pragma unroll
    for (int mt = 0; mt < 4; mt++) {
        const int mr0 = m0 + wm * 64 + mt * 16 + g;
        const int mr1 = mr0 + 8;
        const float s0 = E[mr0], s1 = E[mr1];
#pragma unroll
        for (int nt = 0; nt < 4; nt++) {
            const int nc = n0 + wn * 32 + nt * 8 + 2 * t;
            float2 v0 = make_float2(acc[mt][nt][0] * s0, acc[mt][nt][1] * s0);
            float2 v1 = make_float2(acc[mt][nt][2] * s1, acc[mt][nt][3] * s1);
            *reinterpret_cast<float2*>(&C[(size_t)mr0 * ldc + nc]) = v0;
            *reinterpret_cast<float2*>(&C[(size_t)mr1 * ldc + nc]) = v1;
        }
    }
}

__launch_bounds__(256, 2)
__global__ void hgemmB(const __half* __restrict__ adjH,
                       const __half* __restrict__ supH,
                       const float* __restrict__ degree,
                       float* __restrict__ out)
{
    extern __shared__ __align__(16) char smem[];
    const uint32_t sb = smem_u32(smem);
    const int n0 = blockIdx.x * BNb;
    if (blockIdx.y < (N_Uc / BMb)) {
        gemmB_body<true>(adjH, supH + (size_t)N_Uc * D_Hc, degree, out,
                         blockIdx.y * BMb, n0, sb);
    } else {
        gemmB_body<false>(adjH, supH, degree + N_Uc,
                          out + (size_t)N_Uc * D_Hc,
                          (blockIdx.y - N_Uc / BMb) * BMb, n0, sb);
    }
}

// ---------------- merged fp32 -> fp16 pre-pass (one launch, 3 tensors) ----------------
#define NELEM0 ((size_t)N_TOTc * D_INc)   // input: 33554432
#define NELEM1 ((size_t)D_Hc * D_INc)     // W:      4194304
#define NELEM2 ((size_t)N_Uc * N_Ic)      // adj:   67108864
#define NELEM_TOT (NELEM0 + NELEM1 + NELEM2)   // 104857600 (=8*13107200)

__global__ void f32_to_f16_all(const float* __restrict__ s0, __half* __restrict__ d0,
                               const float* __restrict__ s1, __half* __restrict__ d1,
                               const float* __restrict__ s2, __half* __restrict__ d2)
{
    size_t i = ((size_t)blockIdx.x * blockDim.x + threadIdx.x) * 8;
    if (i < NELEM0) {
        cvt8(s0 + i, d0 + i);
    } else if (i < NELEM0 + NELEM1) {
        size_t j = i - NELEM0;
        cvt8(s1 + j, d1 + j);
    } else {
        size_t j = i - NELEM0 - NELEM1;
        cvt8(s2 + j, d2 + j);
    }
}

// ---------------- launch ----------------
extern "C" void kernel_launch(void* const* d_in, const int* in_sizes, int n_in,
                              void* d_out, int out_size)
{
    const float* input  = (const float*)d_in[0];
    const float* adj    = (const float*)d_in[1];
    const float* degree = (const float*)d_in[2];
    const float* W      = (const float*)d_in[3];
    const float* b      = (const float*)d_in[4];
    float* out = (float*)d_out;

    __half *inputH, *WH, *adjH, *supH;
    cudaGetSymbolAddress((void**)&inputH, g_inputH);
    cudaGetSymbolAddress((void**)&WH, g_WH);
    cudaGetSymbolAddress((void**)&adjH, g_adjH);
    cudaGetSymbolAddress((void**)&supH, g_supH);

    cudaFuncSetAttribute(hgemmA, cudaFuncAttributeMaxDynamicSharedMemorySize, SMEM_A_TOTAL);
    cudaFuncSetAttribute(hgemmB, cudaFuncAttributeMaxDynamicSharedMemorySize, SMEM_B_TOTAL);

    // single merged pre-pass: rn(input), rn(W), rn(adj)
    {
        const int nthr = 256;
        const size_t nblk = NELEM_TOT / 8 / nthr;   // 51200
        f32_to_f16_all<<<(unsigned)nblk, nthr>>>(input, inputH, W, WH, adj, adjH);
    }

    // GEMM1: supH = rn( input @ W^T + b )
    {
        dim3 grid(D_Hc / BNa, N_TOTc / BMa);
        hgemmA<<<grid, 128, SMEM_A_TOTAL>>>(
            inputH, WH, b, supH, D_INc, D_INc, D_INc, D_Hc);
    }
    // GEMM2 + GEMM3 merged
    {
        dim3 grid(D_Hc / BNb, (N_Uc + N_Ic) / BMb);   // (16, 128)
        hgemmB<<<grid, 256, SMEM_B_TOTAL>>>(adjH, supH, degree, out);
    }
}

// round 14
// speedup vs baseline: 1.0053x; 1.0053x over previous
#include <cuda_runtime.h>
#include <cuda_fp16.h>
#include <cstdint>
#include <cstddef>

// ---------------- problem constants ----------------
#define N_Uc   8192
#define N_Ic   8192
#define D_INc  2048
#define D_Hc   2048
#define N_TOTc (N_Uc + N_Ic)

// ---------------- fp16 scratch (device globals; no allocs allowed) ----------------
__device__ __half g_inputH[(size_t)N_TOTc * D_INc];   // rn(input)  [16384][2048]
__device__ __half g_WH[(size_t)D_Hc * D_INc];         // rn(W)      [2048][2048]
__device__ __half g_adjH[(size_t)N_Uc * N_Ic];        // rn(adj)    [8192][8192]
__device__ __half g_supH[(size_t)N_TOTc * D_Hc];      // rn(support)[16384][2048]

// ---------------- PTX helpers ----------------
__device__ __forceinline__ uint32_t smem_u32(const void* p) {
    uint32_t a;
    asm("{ .reg .u64 t; cvta.to.shared.u64 t, %1; cvt.u32.u64 %0, t; }" : "=r"(a) : "l"(p));
    return a;
}
__device__ __forceinline__ void cp_async16(uint32_t s, const void* g) {
    asm volatile("cp.async.cg.shared.global [%0], [%1], 16;" :: "r"(s), "l"(g));
}
__device__ __forceinline__ void cp_commit() {
    asm volatile("cp.async.commit_group;" ::: "memory");
}
template<int N>
__device__ __forceinline__ void cp_wait() {
    asm volatile("cp.async.wait_group %0;" :: "n"(N) : "memory");
}
__device__ __forceinline__ void ldsm_x4(uint32_t& r0, uint32_t& r1, uint32_t& r2,
                                        uint32_t& r3, uint32_t addr) {
    asm volatile("ldmatrix.sync.aligned.m8n8.x4.shared.b16 {%0,%1,%2,%3}, [%4];"
                 : "=r"(r0), "=r"(r1), "=r"(r2), "=r"(r3) : "r"(addr));
}
__device__ __forceinline__ void ldsm_x4_t(uint32_t& r0, uint32_t& r1, uint32_t& r2,
                                          uint32_t& r3, uint32_t addr) {
    asm volatile("ldmatrix.sync.aligned.m8n8.x4.trans.shared.b16 {%0,%1,%2,%3}, [%4];"
                 : "=r"(r0), "=r"(r1), "=r"(r2), "=r"(r3) : "r"(addr));
}
__device__ __forceinline__ void mma_f16(float d[4], const uint32_t a[4],
                                        const uint32_t b[2], const float c[4]) {
    asm volatile(
        "mma.sync.aligned.m16n8k16.row.col.f32.f16.f16.f32 "
        "{%0,%1,%2,%3}, {%4,%5,%6,%7}, {%8,%9}, {%10,%11,%12,%13};"
        : "=f"(d[0]), "=f"(d[1]), "=f"(d[2]), "=f"(d[3])
        : "r"(a[0]), "r"(a[1]), "r"(a[2]), "r"(a[3]),
          "r"(b[0]), "r"(b[1]),
          "f"(c[0]), "f"(c[1]), "f"(c[2]), "f"(c[3]));
}

__device__ __forceinline__ void cvt8(const float* __restrict__ src,
                                     __half* __restrict__ dst) {
    float4 v0 = *reinterpret_cast<const float4*>(src);
    float4 v1 = *reinterpret_cast<const float4*>(src + 4);
    __half2 h0 = __floats2half2_rn(v0.x, v0.y);
    __half2 h1 = __floats2half2_rn(v0.z, v0.w);
    __half2 h2 = __floats2half2_rn(v1.x, v1.y);
    __half2 h3 = __floats2half2_rn(v1.z, v1.w);
    uint4 u;
    u.x = *reinterpret_cast<uint32_t*>(&h0);
    u.y = *reinterpret_cast<uint32_t*>(&h1);
    u.z = *reinterpret_cast<uint32_t*>(&h2);
    u.w = *reinterpret_cast<uint32_t*>(&h3);
    *reinterpret_cast<uint4*>(dst) = u;
}

// ============================================================================
// Kernel A = adj-converter side-band (LOW block ids -> wave 1, overlaps
// GEMM1's idle DRAM) + GEMM1.
// GEMM1: CTA 128x128x64, 4 warps (2x2), warp 64x64, 3-stage, single
// __syncthreads/iter, 2 CTAs/SM. A K-contig, B [n][k] K-contig.
// adjH is consumed only by kernel B (next launch) -> ordered by kernel boundary.
// ============================================================================
#define BMa 128
#define BNa 128
#define BKa 64
#define NSTGa 3
#define SKCa 144    // 64 halves = 128B -> 144
#define ASZa (BMa * SKCa)
#define BSZa (BNa * SKCa)
#define STGa (ASZa + BSZa)
#define SMEM_A_TOTAL (NSTGa * STGa)   // 110592
#define CONV_ROWS 8                   // converters: blockIdx.y < 8 -> ids 0..127

__launch_bounds__(128, 2)
__global__ void hgemmA(const __half* __restrict__ A, const __half* __restrict__ B,
                       const float* __restrict__ E, __half* __restrict__ C,
                       const float* __restrict__ adjF, __half* __restrict__ adjHo,
                       int K, int lda, int ldb, int ldc)
{
    const int tid = threadIdx.x;

    // ---------------- converter side-band (scheduled FIRST) ----------------
    if (blockIdx.y < CONV_ROWS) {
        const int NCONV = CONV_ROWS * 16;                 // 128 CTAs
        const int cid = blockIdx.y * gridDim.x + blockIdx.x;
        const size_t total = (size_t)N_Uc * N_Ic;         // 64M elems
        const size_t per = total / NCONV;                 // 512K elems/CTA
        const size_t base = (size_t)cid * per;
        for (size_t i = base + (size_t)tid * 8; i < base + per; i += 128 * 8)
            cvt8(adjF + i, adjHo + i);
        return;
    }

    // ---------------- GEMM1 ----------------
    extern __shared__ __align__(16) char smem[];
    const uint32_t sb = smem_u32(smem);

    const int lane = tid & 31;
    const int warp = tid >> 5;
    const int wm   = warp >> 1;
    const int wn   = warp & 1;
    const int q    = lane >> 3;
    const int r    = lane & 7;
    const int g    = lane >> 2;
    const int t    = lane & 3;

    const int m0 = (blockIdx.y - CONV_ROWS) * BMa;
    const int n0 = blockIdx.x * BNa;

    float acc[4][8][4];
#pragma unroll
    for (int i = 0; i < 4; i++)
#pragma unroll
        for (int j = 0; j < 8; j++)
#pragma unroll
            for (int k = 0; k < 4; k++) acc[i][j][k] = 0.f;

    const uint32_t a_base = (uint32_t)((wm * 64 + r + (q & 1) * 8) * SKCa + (q >> 1) * 16);
    const uint32_t b_base = (uint32_t)((wn * 64 + r + (q >> 1) * 8) * SKCa + (q & 1) * 16);

    auto fill = [&](int s, int kt) {
        const uint32_t ab = sb + (uint32_t)s * STGa;
        const uint32_t bb = ab + ASZa;
        const int k0 = kt * BKa;
#pragma unroll
        for (int i = 0; i < 8; i++) {
            int ci = tid + i * 128, row = ci >> 3, c = ci & 7;
            cp_async16(ab + row * SKCa + c * 16,
                       A + (size_t)(m0 + row) * lda + k0 + c * 8);
        }
#pragma unroll
        for (int i = 0; i < 8; i++) {
            int ci = tid + i * 128, row = ci >> 3, c = ci & 7;
            cp_async16(bb + row * SKCa + c * 16,
                       B + (size_t)(n0 + row) * ldb + k0 + c * 8);
        }
        cp_commit();
    };

    const int T = K / BKa;
    fill(0, 0);
    fill(1, 1);

    int s = 0;
    for (int kt = 0; kt < T; kt++) {
        cp_wait<1>();
        __syncthreads();
        if (kt + 2 < T) {
            int ns = s + 2; if (ns >= NSTGa) ns -= NSTGa;
            fill(ns, kt + 2);
        } else {
            cp_commit();
        }

        const uint32_t aa = sb + (uint32_t)s * STGa + a_base;
        const uint32_t ba = sb + (uint32_t)s * STGa + ASZa + b_base;
#pragma unroll
        for (int ks = 0; ks < 4; ks++) {
            const uint32_t ak = aa + ks * 32;
            const uint32_t bk = ba + ks * 32;
            uint32_t af[4][4];
#pragma unroll
            for (int mt = 0; mt < 4; mt++)
                ldsm_x4(af[mt][0], af[mt][1], af[mt][2], af[mt][3], ak + mt * 16 * SKCa);
            uint32_t bf[8][2];
#pragma unroll
            for (int h = 0; h < 4; h++)
                ldsm_x4(bf[2*h][0], bf[2*h][1], bf[2*h+1][0], bf[2*h+1][1], bk + h * 16 * SKCa);
#pragma unroll
            for (int mt = 0; mt < 4; mt++)
#pragma unroll
                for (int nt = 0; nt < 8; nt++)
                    mma_f16(acc[mt][nt], af[mt], bf[nt], acc[mt][nt]);
        }
        if (++s == NSTGa) s = 0;
    }

#pragma unroll
    for (int mt = 0; mt < 4; mt++) {
        const int mr0 = m0 + wm * 64 + mt * 16 + g;
        const int mr1 = mr0 + 8;
#pragma unroll
        for (int nt = 0; nt < 8; nt++) {
            const int nc = n0 + wn * 64 + nt * 8 + 2 * t;
            const float bx = E[nc], by = E[nc + 1];
            *reinterpret_cast<__half2*>(&C[(size_t)mr0 * ldc + nc]) =
                __floats2half2_rn(acc[mt][nt][0] + bx, acc[mt][nt][1] + by);
            *reinterpret_cast<__half2*>(&C[(size_t)mr1 * ldc + nc]) =
                __floats2half2_rn(acc[mt][nt][2] + bx, acc[mt][nt][3] + by);
        }
    }
}

// ============================================================================
// Kernel B (GEMM2+GEMM3 merged): CTA 128x128x64, 8 warps (2x4), warp 64x32,
// 3-stage, single __syncthreads/iter, 2 CTAs/SM, hoisted/pipelined ldmatrix.
// (Round-13 form, tensor 64%.)
// ============================================================================
#define BMb 128
#define BNb 128
#define BKb 64
#define NSTGb 3
#define SKCb 144
#define SMCb 272
#define ASZb 18432  // max(128*144, 64*272)
#define BSZb (BKb * SMCb)              // 17408
#define STGb (ASZb + BSZb)             // 35840
#define SMEM_B_TOTAL (NSTGb * STGb)    // 107520

template<bool A_K_CONTIG>
__device__ __forceinline__ void gemmB_body(
    const __half* __restrict__ A, const __half* __restrict__ B,
    const float* __restrict__ E, float* __restrict__ C,
    int m0, int n0, uint32_t sb)
{
    const int K   = 8192;
    const int lda = N_Ic;
    const int ldb = D_Hc;
    const int ldc = D_Hc;

    const int tid  = threadIdx.x;
    const int lane = tid & 31;
    const int warp = tid >> 5;
    const int wm   = warp >> 2;
    const int wn   = warp & 3;
    const int q    = lane >> 3;
    const int r    = lane & 7;
    const int g    = lane >> 2;
    const int t    = lane & 3;

    float acc[4][4][4];
#pragma unroll
    for (int i = 0; i < 4; i++)
#pragma unroll
        for (int j = 0; j < 4; j++)
#pragma unroll
            for (int k = 0; k < 4; k++) acc[i][j][k] = 0.f;

    uint32_t a_base;
    if (A_K_CONTIG)
        a_base = (uint32_t)((wm * 64 + r + (q & 1) * 8) * SKCb + (q >> 1) * 16);
    else
        a_base = (uint32_t)((r + (q >> 1) * 8) * SMCb + (wm * 64 + (q & 1) * 8) * 2);
    const uint32_t b_base =
        (uint32_t)((r + (q & 1) * 8) * SMCb + (wn * 32 + (q >> 1) * 8) * 2);

    auto fill = [&](int s, int kt) {
        const uint32_t ab = sb + (uint32_t)s * STGb;
        const uint32_t bb = ab + ASZb;
        const int k0 = kt * BKb;
        if (A_K_CONTIG) {
#pragma unroll
            for (int i = 0; i < 4; i++) {
                int ci = tid + i * 256, row = ci >> 3, c = ci & 7;
                cp_async16(ab + row * SKCb + c * 16,
                           A + (size_t)(m0 + row) * lda + k0 + c * 8);
            }
        } else {
#pragma unroll
            for (int i = 0; i < 4; i++) {
                int ci = tid + i * 256, row = ci >> 4, c = ci & 15;
                cp_async16(ab + row * SMCb + c * 16,
                           A + (size_t)(k0 + row) * lda + m0 + c * 8);
            }
        }
#pragma unroll
        for (int i = 0; i < 4; i++) {
            int ci = tid + i * 256, row = ci >> 4, c = ci & 15;
            cp_async16(bb + row * SMCb + c * 16,
                       B + (size_t)(k0 + row) * ldb + n0 + c * 8);
        }
        cp_commit();
    };

    auto load_a = [&](uint32_t aa, int ks, uint32_t af[4][4]) {
        const uint32_t ak = A_K_CONTIG ? (aa + ks * 32) : (aa + ks * 16 * SMCb);
#pragma unroll
        for (int mt = 0; mt < 4; mt++) {
            const uint32_t addr = A_K_CONTIG ? (ak + mt * 16 * SKCb) : (ak + mt * 32);
            if (A_K_CONTIG) ldsm_x4  (af[mt][0], af[mt][1], af[mt][2], af[mt][3], addr);
            else            ldsm_x4_t(af[mt][0], af[mt][1], af[mt][2], af[mt][3], addr);
        }
    };
    auto load_b = [&](uint32_t ba, int ks, uint32_t bf[4][2]) {
        const uint32_t bk = ba + ks * 16 * SMCb;
#pragma unroll
        for (int h = 0; h < 2; h++)
            ldsm_x4_t(bf[2*h][0], bf[2*h][1], bf[2*h+1][0], bf[2*h+1][1], bk + h * 32);
    };

    const int T = K / BKb;
    fill(0, 0);
    fill(1, 1);

    int s = 0;
    for (int kt = 0; kt < T; kt++) {
        cp_wait<1>();
        __syncthreads();

        const uint32_t aa = sb + (uint32_t)s * STGb + a_base;
        const uint32_t ba = sb + (uint32_t)s * STGb + ASZb + b_base;

        uint32_t af[4][4], bf[4][2];
        load_a(aa, 0, af);
        load_b(ba, 0, bf);

        if (kt + 2 < T) {
            int ns = s + 2; if (ns >= NSTGb) ns -= NSTGb;
            fill(ns, kt + 2);
        } else {
            cp_commit();
        }

#pragma unroll
        for (int ks = 0; ks < 4; ks++) {
#pragma unroll
            for (int mt = 0; mt < 4; mt++)
#pragma unroll
                for (int nt = 0; nt < 4; nt++)
                    mma_f16(acc[mt][nt], af[mt], bf[nt], acc[mt][nt]);
            if (ks < 3) {
                load_a(aa, ks + 1, af);
                load_b(ba, ks + 1, bf);
            }
        }
        if (++s == NSTGb) s = 0;
    }

#pragma unroll
    for (int mt = 0; mt < 4; mt++) {
        const int mr0 = m0 + wm * 64 + mt * 16 + g;
        const int mr1 = mr0 + 8;
        const float s0 = E[mr0], s1 = E[mr1];
#pragma unroll
        for (int nt = 0; nt < 4; nt++) {
            const int nc = n0 + wn * 32 + nt * 8 + 2 * t;
            float2 v0 = make_float2(acc[mt][nt][0] * s0, acc[mt][nt][1] * s0);
            float2 v1 = make_float2(acc[mt][nt][2] * s1, acc[mt][nt][3] * s1);
            *reinterpret_cast<float2*>(&C[(size_t)mr0 * ldc + nc]) = v0;
            *reinterpret_cast<float2*>(&C[(size_t)mr1 * ldc + nc]) = v1;
        }
    }
}

__launch_bounds__(256, 2)
__global__ void hgemmB(const __half* __restrict__ adjH,
                       const __half* __restrict__ supH,
                       const float* __restrict__ degree,
                       float* __restrict__ out)
{
    extern __shared__ __align__(16) char smem[];
    const uint32_t sb = smem_u32(smem);
    const int n0 = blockIdx.x * BNb;
    if (blockIdx.y < (N_Uc / BMb)) {
        gemmB_body<true>(adjH, supH + (size_t)N_Uc * D_Hc, degree, out,
                         blockIdx.y * BMb, n0, sb);
    } else {
        gemmB_body<false>(adjH, supH, degree + N_Uc,
                          out + (size_t)N_Uc * D_Hc,
                          (blockIdx.y - N_Uc / BMb) * BMb, n0, sb);
    }
}

// ---------------- fp32 -> fp16 pre-pass (input + W only; adj overlaps GEMM1) ----------------
#define NELEM0 ((size_t)N_TOTc * D_INc)   // input: 33554432
#define NELEM1 ((size_t)D_Hc * D_INc)     // W:      4194304
#define NELEM_IW (NELEM0 + NELEM1)        // 37748736 (=8*4718592)

__global__ void f32_to_f16_iw(const float* __restrict__ s0, __half* __restrict__ d0,
                              const float* __restrict__ s1, __half* __restrict__ d1)
{
    size_t i = ((size_t)blockIdx.x * blockDim.x + threadIdx.x) * 8;
    if (i < NELEM0) {
        cvt8(s0 + i, d0 + i);
    } else {
        size_t j = i - NELEM0;
        cvt8(s1 + j, d1 + j);
    }
}

// ---------------- launch ----------------
extern "C" void kernel_launch(void* const* d_in, const int* in_sizes, int n_in,
                              void* d_out, int out_size)
{
    const float* input  = (const float*)d_in[0];
    const float* adj    = (const float*)d_in[1];
    const float* degree = (const float*)d_in[2];
    const float* W      = (const float*)d_in[3];
    const float* b      = (const float*)d_in[4];
    float* out = (float*)d_out;

    __half *inputH, *WH, *adjH, *supH;
    cudaGetSymbolAddress((void**)&inputH, g_inputH);
    cudaGetSymbolAddress((void**)&WH, g_WH);
    cudaGetSymbolAddress((void**)&adjH, g_adjH);
    cudaGetSymbolAddress((void**)&supH, g_supH);

    cudaFuncSetAttribute(hgemmA, cudaFuncAttributeMaxDynamicSharedMemorySize, SMEM_A_TOTAL);
    cudaFuncSetAttribute(hgemmB, cudaFuncAttributeMaxDynamicSharedMemorySize, SMEM_B_TOTAL);

    // pre-pass: rn(input), rn(W) only (adj converts inside hgemmA's launch)
    {
        const int nthr = 256;
        const size_t nblk = NELEM_IW / 8 / nthr;   // 18432
        f32_to_f16_iw<<<(unsigned)nblk, nthr>>>(input, inputH, W, WH);
    }

    // GEMM1 (+ adj conversion in wave 1, low block ids)
    {
        dim3 grid(D_Hc / BNa, CONV_ROWS + N_TOTc / BMa);   // (16, 136)
        hgemmA<<<grid, 128, SMEM_A_TOTAL>>>(
            inputH, WH, b, supH, adj, adjH, D_INc, D_INc, D_INc, D_Hc);
    }
    // GEMM2 + GEMM3 merged
    {
        dim3 grid(D_Hc / BNb, (N_Uc + N_Ic) / BMb);   // (16, 128)
        hgemmB<<<grid, 256, SMEM_B_TOTAL>>>(adjH, supH, degree, out);
    }
}

// round 15
// speedup vs baseline: 1.0053x; 1.0000x over previous
#include <cuda_runtime.h>
#include <cuda_fp16.h>
#include <cstdint>
#include <cstddef>

// ---------------- problem constants ----------------
#define N_Uc   8192
#define N_Ic   8192
#define D_INc  2048
#define D_Hc   2048
#define N_TOTc (N_Uc + N_Ic)

// ---------------- fp16 scratch (device globals; no allocs allowed) ----------------
__device__ __half g_inputH[(size_t)N_TOTc * D_INc];   // rn(input)  [16384][2048]
__device__ __half g_WH[(size_t)D_Hc * D_INc];         // rn(W)      [2048][2048]
__device__ __half g_adjH[(size_t)N_Uc * N_Ic];        // rn(adj)    [8192][8192]
__device__ __half g_supH[(size_t)N_TOTc * D_Hc];      // rn(support)[16384][2048]

// ---------------- PTX helpers ----------------
__device__ __forceinline__ uint32_t smem_u32(const void* p) {
    uint32_t a;
    asm("{ .reg .u64 t; cvta.to.shared.u64 t, %1; cvt.u32.u64 %0, t; }" : "=r"(a) : "l"(p));
    return a;
}
__device__ __forceinline__ void cp_async16(uint32_t s, const void* g) {
    asm volatile("cp.async.cg.shared.global [%0], [%1], 16;" :: "r"(s), "l"(g));
}
__device__ __forceinline__ void cp_commit() {
    asm volatile("cp.async.commit_group;" ::: "memory");
}
template<int N>
__device__ __forceinline__ void cp_wait() {
    asm volatile("cp.async.wait_group %0;" :: "n"(N) : "memory");
}
__device__ __forceinline__ void ldsm_x4(uint32_t& r0, uint32_t& r1, uint32_t& r2,
                                        uint32_t& r3, uint32_t addr) {
    asm volatile("ldmatrix.sync.aligned.m8n8.x4.shared.b16 {%0,%1,%2,%3}, [%4];"
                 : "=r"(r0), "=r"(r1), "=r"(r2), "=r"(r3) : "r"(addr));
}
__device__ __forceinline__ void ldsm_x4_t(uint32_t& r0, uint32_t& r1, uint32_t& r2,
                                          uint32_t& r3, uint32_t addr) {
    asm volatile("ldmatrix.sync.aligned.m8n8.x4.trans.shared.b16 {%0,%1,%2,%3}, [%4];"
                 : "=r"(r0), "=r"(r1), "=r"(r2), "=r"(r3) : "r"(addr));
}
__device__ __forceinline__ void mma_f16(float d[4], const uint32_t a[4],
                                        const uint32_t b[2], const float c[4]) {
    asm volatile(
        "mma.sync.aligned.m16n8k16.row.col.f32.f16.f16.f32 "
        "{%0,%1,%2,%3}, {%4,%5,%6,%7}, {%8,%9}, {%10,%11,%12,%13};"
        : "=f"(d[0]), "=f"(d[1]), "=f"(d[2]), "=f"(d[3])
        : "r"(a[0]), "r"(a[1]), "r"(a[2]), "r"(a[3]),
          "r"(b[0]), "r"(b[1]),
          "f"(c[0]), "f"(c[1]), "f"(c[2]), "f"(c[3]));
}

__device__ __forceinline__ void cvt8(const float* __restrict__ src,
                                     __half* __restrict__ dst) {
    float4 v0 = *reinterpret_cast<const float4*>(src);
    float4 v1 = *reinterpret_cast<const float4*>(src + 4);
    __half2 h0 = __floats2half2_rn(v0.x, v0.y);
    __half2 h1 = __floats2half2_rn(v0.z, v0.w);
    __half2 h2 = __floats2half2_rn(v1.x, v1.y);
    __half2 h3 = __floats2half2_rn(v1.z, v1.w);
    uint4 u;
    u.x = *reinterpret_cast<uint32_t*>(&h0);
    u.y = *reinterpret_cast<uint32_t*>(&h1);
    u.z = *reinterpret_cast<uint32_t*>(&h2);
    u.w = *reinterpret_cast<uint32_t*>(&h3);
    *reinterpret_cast<uint4*>(dst) = u;
}

// ============================================================================
// Kernel A = adj-converter side-band (LOW block ids -> wave 1, overlaps
// GEMM1's idle DRAM) + GEMM1.
// GEMM1: CTA 128x128x64, 4 warps (2x2), warp 64x64, 3-stage, single
// __syncthreads/iter, 2 CTAs/SM. A K-contig, B [n][k] K-contig.
// adjH is consumed only by kernel B (next launch) -> ordered by kernel boundary.
// ============================================================================
#define BMa 128
#define BNa 128
#define BKa 64
#define NSTGa 3
#define SKCa 144    // 64 halves = 128B -> 144
#define ASZa (BMa * SKCa)
#define BSZa (BNa * SKCa)
#define STGa (ASZa + BSZa)
#define SMEM_A_TOTAL (NSTGa * STGa)   // 110592
#define CONV_ROWS 8                   // converters: blockIdx.y < 8 -> ids 0..127

__launch_bounds__(128, 2)
__global__ void hgemmA(const __half* __restrict__ A, const __half* __restrict__ B,
                       const float* __restrict__ E, __half* __restrict__ C,
                       const float* __restrict__ adjF, __half* __restrict__ adjHo,
                       int K, int lda, int ldb, int ldc)
{
    const int tid = threadIdx.x;

    // ---------------- converter side-band (scheduled FIRST) ----------------
    if (blockIdx.y < CONV_ROWS) {
        const int NCONV = CONV_ROWS * 16;                 // 128 CTAs
        const int cid = blockIdx.y * gridDim.x + blockIdx.x;
        const size_t total = (size_t)N_Uc * N_Ic;         // 64M elems
        const size_t per = total / NCONV;                 // 512K elems/CTA
        const size_t base = (size_t)cid * per;
        for (size_t i = base + (size_t)tid * 8; i < base + per; i += 128 * 8)
            cvt8(adjF + i, adjHo + i);
        return;
    }

    // ---------------- GEMM1 ----------------
    extern __shared__ __align__(16) char smem[];
    const uint32_t sb = smem_u32(smem);

    const int lane = tid & 31;
    const int warp = tid >> 5;
    const int wm   = warp >> 1;
    const int wn   = warp & 1;
    const int q    = lane >> 3;
    const int r    = lane & 7;
    const int g    = lane >> 2;
    const int t    = lane & 3;

    const int m0 = (blockIdx.y - CONV_ROWS) * BMa;
    const int n0 = blockIdx.x * BNa;

    float acc[4][8][4];
#pragma unroll
    for (int i = 0; i < 4; i++)
#pragma unroll
        for (int j = 0; j < 8; j++)
#pragma unroll
            for (int k = 0; k < 4; k++) acc[i][j][k] = 0.f;

    const uint32_t a_base = (uint32_t)((wm * 64 + r + (q & 1) * 8) * SKCa + (q >> 1) * 16);
    const uint32_t b_base = (uint32_t)((wn * 64 + r + (q >> 1) * 8) * SKCa + (q & 1) * 16);

    auto fill = [&](int s, int kt) {
        const uint32_t ab = sb + (uint32_t)s * STGa;
        const uint32_t bb = ab + ASZa;
        const int k0 = kt * BKa;
#pragma unroll
        for (int i = 0; i < 8; i++) {
            int ci = tid + i * 128, row = ci >> 3, c = ci & 7;
            cp_async16(ab + row * SKCa + c * 16,
                       A + (size_t)(m0 + row) * lda + k0 + c * 8);
        }
#pragma unroll
        for (int i = 0; i < 8; i++) {
            int ci = tid + i * 128, row = ci >> 3, c = ci & 7;
            cp_async16(bb + row * SKCa + c * 16,
                       B + (size_t)(n0 + row) * ldb + k0 + c * 8);
        }
        cp_commit();
    };

    const int T = K / BKa;
    fill(0, 0);
    fill(1, 1);

    int s = 0;
    for (int kt = 0; kt < T; kt++) {
        cp_wait<1>();
        __syncthreads();
        if (kt + 2 < T) {
            int ns = s + 2; if (ns >= NSTGa) ns -= NSTGa;
            fill(ns, kt + 2);
        } else {
            cp_commit();
        }

        const uint32_t aa = sb + (uint32_t)s * STGa + a_base;
        const uint32_t ba = sb + (uint32_t)s * STGa + ASZa + b_base;
#pragma unroll
        for (int ks = 0; ks < 4; ks++) {
            const uint32_t ak = aa + ks * 32;
            const uint32_t bk = ba + ks * 32;
            uint32_t af[4][4];
#pragma unroll
            for (int mt = 0; mt < 4; mt++)
                ldsm_x4(af[mt][0], af[mt][1], af[mt][2], af[mt][3], ak + mt * 16 * SKCa);
            uint32_t bf[8][2];
#pragma unroll
            for (int h = 0; h < 4; h++)
                ldsm_x4(bf[2*h][0], bf[2*h][1], bf[2*h+1][0], bf[2*h+1][1], bk + h * 16 * SKCa);
#pragma unroll
            for (int mt = 0; mt < 4; mt++)
#pragma unroll
                for (int nt = 0; nt < 8; nt++)
                    mma_f16(acc[mt][nt], af[mt], bf[nt], acc[mt][nt]);
        }
        if (++s == NSTGa) s = 0;
    }

#pragma unroll
    for (int mt = 0; mt < 4; mt++) {
        const int mr0 = m0 + wm * 64 + mt * 16 + g;
        const int mr1 = mr0 + 8;
#pragma unroll
        for (int nt = 0; nt < 8; nt++) {
            const int nc = n0 + wn * 64 + nt * 8 + 2 * t;
            const float bx = E[nc], by = E[nc + 1];
            *reinterpret_cast<__half2*>(&C[(size_t)mr0 * ldc + nc]) =
                __floats2half2_rn(acc[mt][nt][0] + bx, acc[mt][nt][1] + by);
            *reinterpret_cast<__half2*>(&C[(size_t)mr1 * ldc + nc]) =
                __floats2half2_rn(acc[mt][nt][2] + bx, acc[mt][nt][3] + by);
        }
    }
}

// ============================================================================
// Kernel B (GEMM2+GEMM3 merged): CTA 128x128x64, 8 warps (2x4), warp 64x32,
// 3-stage, single __syncthreads/iter, 2 CTAs/SM, hoisted/pipelined ldmatrix.
// (Round-13 form, tensor 64%.)
// ============================================================================
#define BMb 128
#define BNb 128
#define BKb 64
#define NSTGb 3
#define SKCb 144
#define SMCb 272
#define ASZb 18432  // max(128*144, 64*272)
#define BSZb (BKb * SMCb)              // 17408
#define STGb (ASZb + BSZb)             // 35840
#define SMEM_B_TOTAL (NSTGb * STGb)    // 107520

template<bool A_K_CONTIG>
__device__ __forceinline__ void gemmB_body(
    const __half* __restrict__ A, const __half* __restrict__ B,
    const float* __restrict__ E, float* __restrict__ C,
    int m0, int n0, uint32_t sb)
{
    const int K   = 8192;
    const int lda = N_Ic;
    const int ldb = D_Hc;
    const int ldc = D_Hc;

    const int tid  = threadIdx.x;
    const int lane = tid & 31;
    const int warp = tid >> 5;
    const int wm   = warp >> 2;
    const int wn   = warp & 3;
    const int q    = lane >> 3;
    const int r    = lane & 7;
    const int g    = lane >> 2;
    const int t    = lane & 3;

    float acc[4][4][4];
#pragma unroll
    for (int i = 0; i < 4; i++)
#pragma unroll
        for (int j = 0; j < 4; j++)
#pragma unroll
            for (int k = 0; k < 4; k++) acc[i][j][k] = 0.f;

    uint32_t a_base;
    if (A_K_CONTIG)
        a_base = (uint32_t)((wm * 64 + r + (q & 1) * 8) * SKCb + (q >> 1) * 16);
    else
        a_base = (uint32_t)((r + (q >> 1) * 8) * SMCb + (wm * 64 + (q & 1) * 8) * 2);
    const uint32_t b_base =
        (uint32_t)((r + (q & 1) * 8) * SMCb + (wn * 32 + (q >> 1) * 8) * 2);

    auto fill = [&](int s, int kt) {
        const uint32_t ab = sb + (uint32_t)s * STGb;
        const uint32_t bb = ab + ASZb;
        const int k0 = kt * BKb;
        if (A_K_CONTIG) {
#pragma unroll
            for (int i = 0; i < 4; i++) {
                int ci = tid + i * 256, row = ci >> 3, c = ci & 7;
                cp_async16(ab + row * SKCb + c * 16,
                           A + (size_t)(m0 + row) * lda + k0 + c * 8);
            }
        } else {
#pragma unroll
            for (int i = 0; i < 4; i++) {
                int ci = tid + i * 256, row = ci >> 4, c = ci & 15;
                cp_async16(ab + row * SMCb + c * 16,
                           A + (size_t)(k0 + row) * lda + m0 + c * 8);
            }
        }
#pragma unroll
        for (int i = 0; i < 4; i++) {
            int ci = tid + i * 256, row = ci >> 4, c = ci & 15;
            cp_async16(bb + row * SMCb + c * 16,
                       B + (size_t)(k0 + row) * ldb + n0 + c * 8);
        }
        cp_commit();
    };

    auto load_a = [&](uint32_t aa, int ks, uint32_t af[4][4]) {
        const uint32_t ak = A_K_CONTIG ? (aa + ks * 32) : (aa + ks * 16 * SMCb);
#pragma unroll
        for (int mt = 0; mt < 4; mt++) {
            const uint32_t addr = A_K_CONTIG ? (ak + mt * 16 * SKCb) : (ak + mt * 32);
            if (A_K_CONTIG) ldsm_x4  (af[mt][0], af[mt][1], af[mt][2], af[mt][3], addr);
            else            ldsm_x4_t(af[mt][0], af[mt][1], af[mt][2], af[mt][3], addr);
        }
    };
    auto load_b = [&](uint32_t ba, int ks, uint32_t bf[4][2]) {
        const uint32_t bk = ba + ks * 16 * SMCb;
#pragma unroll
        for (int h = 0; h < 2; h++)
            ldsm_x4_t(bf[2*h][0], bf[2*h][1], bf[2*h+1][0], bf[2*h+1][1], bk + h * 32);
    };

    const int T = K / BKb;
    fill(0, 0);
    fill(1, 1);

    int s = 0;
    for (int kt = 0; kt < T; kt++) {
        cp_wait<1>();
        __syncthreads();

        const uint32_t aa = sb + (uint32_t)s * STGb + a_base;
        const uint32_t ba = sb + (uint32_t)s * STGb + ASZb + b_base;

        uint32_t af[4][4], bf[4][2];
        load_a(aa, 0, af);
        load_b(ba, 0, bf);

        if (kt + 2 < T) {
            int ns = s + 2; if (ns >= NSTGb) ns -= NSTGb;
            fill(ns, kt + 2);
        } else {
            cp_commit();
        }

#pragma unroll
        for (int ks = 0; ks < 4; ks++) {
#pragma unroll
            for (int mt = 0; mt < 4; mt++)
#pragma unroll
                for (int nt = 0; nt < 4; nt++)
                    mma_f16(acc[mt][nt], af[mt], bf[nt], acc[mt][nt]);
            if (ks < 3) {
                load_a(aa, ks + 1, af);
                load_b(ba, ks + 1, bf);
            }
        }
        if (++s == NSTGb) s = 0;
    }

#pragma unroll
    for (int mt = 0; mt < 4; mt++) {
        const int mr0 = m0 + wm * 64 + mt * 16 + g;
        const int mr1 = mr0 + 8;
        const float s0 = E[mr0], s1 = E[mr1];
#pragma unroll
        for (int nt = 0; nt < 4; nt++) {
            const int nc = n0 + wn * 32 + nt * 8 + 2 * t;
            float2 v0 = make_float2(acc[mt][nt][0] * s0, acc[mt][nt][1] * s0);
            float2 v1 = make_float2(acc[mt][nt][2] * s1, acc[mt][nt][3] * s1);
            *reinterpret_cast<float2*>(&C[(size_t)mr0 * ldc + nc]) = v0;
            *reinterpret_cast<float2*>(&C[(size_t)mr1 * ldc + nc]) = v1;
        }
    }
}

__launch_bounds__(256, 2)
__global__ void hgemmB(const __half* __restrict__ adjH,
                       const __half* __restrict__ supH,
                       const float* __restrict__ degree,
                       float* __restrict__ out)
{
    extern __shared__ __align__(16) char smem[];
    const uint32_t sb = smem_u32(smem);
    const int n0 = blockIdx.x * BNb;
    if (blockIdx.y < (N_Uc / BMb)) {
        gemmB_body<true>(adjH, supH + (size_t)N_Uc * D_Hc, degree, out,
                         blockIdx.y * BMb, n0, sb);
    } else {
        gemmB_body<false>(adjH, supH, degree + N_Uc,
                          out + (size_t)N_Uc * D_Hc,
                          (blockIdx.y - N_Uc / BMb) * BMb, n0, sb);
    }
}

// ---------------- fp32 -> fp16 pre-pass (input + W only; adj overlaps GEMM1) ----------------
#define NELEM0 ((size_t)N_TOTc * D_INc)   // input: 33554432
#define NELEM1 ((size_t)D_Hc * D_INc)     // W:      4194304
#define NELEM_IW (NELEM0 + NELEM1)        // 37748736 (=8*4718592)

__global__ void f32_to_f16_iw(const float* __restrict__ s0, __half* __restrict__ d0,
                              const float* __restrict__ s1, __half* __restrict__ d1)
{
    size_t i = ((size_t)blockIdx.x * blockDim.x + threadIdx.x) * 8;
    if (i < NELEM0) {
        cvt8(s0 + i, d0 + i);
    } else {
        size_t j = i - NELEM0;
        cvt8(s1 + j, d1 + j);
    }
}

// ---------------- launch ----------------
extern "C" void kernel_launch(void* const* d_in, const int* in_sizes, int n_in,
                              void* d_out, int out_size)
{
    const float* input  = (const float*)d_in[0];
    const float* adj    = (const float*)d_in[1];
    const float* degree = (const float*)d_in[2];
    const float* W      = (const float*)d_in[3];
    const float* b      = (const float*)d_in[4];
    float* out = (float*)d_out;

    __half *inputH, *WH, *adjH, *supH;
    cudaGetSymbolAddress((void**)&inputH, g_inputH);
    cudaGetSymbolAddress((void**)&WH, g_WH);
    cudaGetSymbolAddress((void**)&adjH, g_adjH);
    cudaGetSymbolAddress((void**)&supH, g_supH);

    cudaFuncSetAttribute(hgemmA, cudaFuncAttributeMaxDynamicSharedMemorySize, SMEM_A_TOTAL);
    cudaFuncSetAttribute(hgemmB, cudaFuncAttributeMaxDynamicSharedMemorySize, SMEM_B_TOTAL);

    // pre-pass: rn(input), rn(W) only (adj converts inside hgemmA's launch)
    {
        const int nthr = 256;
        const size_t nblk = NELEM_IW / 8 / nthr;   // 18432
        f32_to_f16_iw<<<(unsigned)nblk, nthr>>>(input, inputH, W, WH);
    }

    // GEMM1 (+ adj conversion in wave 1, low block ids)
    {
        dim3 grid(D_Hc / BNa, CONV_ROWS + N_TOTc / BMa);   // (16, 136)
        hgemmA<<<grid, 128, SMEM_A_TOTAL>>>(
            inputH, WH, b, supH, adj, adjH, D_INc, D_INc, D_INc, D_Hc);
    }
    // GEMM2 + GEMM3 merged
    {
        dim3 grid(D_Hc / BNb, (N_Uc + N_Ic) / BMb);   // (16, 128)
        hgemmB<<<grid, 256, SMEM_B_TOTAL>>>(adjH, supH, degree, out);
    }
}